// round 6
// baseline (speedup 1.0000x reference)
#include <cuda_runtime.h>
#include <cuda_fp16.h>
#include <cstdint>

// Problem constants (fixed by the reference).
#define D_IN_   2048
#define D_SAE_  32768
#define N_      8192
#define K_      64

// Gather tiling: CD dims per chunk (fp16 footprint 32768*CD*2 = 16MB,
// L2-resident). RN rows per CTA.
#define CD      256
#define RN      16

// Scratch (device globals — no allocation allowed in kernel_launch).
__device__ __half g_Wth[(size_t)D_SAE_ * D_IN_];  // transposed W, fp16: (D_SAE, D_IN)
__device__ float  g_vals[N_ * K_];                // deduped values

// ---------------------------------------------------------------------------
// Kernel 1 (fused): transpose+convert W_dec (D_IN, D_SAE) fp32 -> g_Wth
// (D_SAE, D_IN) fp16, AND dedupe values (folded into the first 2048 blocks).
// Tile 32 s x 64 d: warp-coalesced 128B reads, __half2-packed 128B writes,
// tile[32][65] conflict-free on both phases. (Measured-good R3 shape.)
// ---------------------------------------------------------------------------
__global__ __launch_bounds__(256)
void transpose_dedupe_kernel(const float* __restrict__ W,
                             const int*   __restrict__ idx,
                             const float* __restrict__ vals) {
    __shared__ float tile[32][65];

    int tx = threadIdx.x & 31;
    int ty = threadIdx.x >> 5;   // 0..7

    int s = blockIdx.x * 32 + tx;
    #pragma unroll
    for (int j = 0; j < 8; ++j) {
        int d = blockIdx.y * 64 + ty * 8 + j;
        tile[tx][ty * 8 + j] = W[(size_t)d * D_SAE_ + s];   // 128B/warp read
    }
    __syncthreads();

    #pragma unroll
    for (int j = 0; j < 4; ++j) {
        int s_local = ty + 8 * j;
        int d_local = tx * 2;
        __half2 h = __floats2half2_rn(tile[s_local][d_local],
                                      tile[s_local][d_local + 1]);
        *reinterpret_cast<__half2*>(
            &g_Wth[(size_t)(blockIdx.x * 32 + s_local) * D_IN_
                   + blockIdx.y * 64 + d_local]) = h;       // 128B/warp write
    }

    // Dedupe (first 2048 blocks; 4 rows each). Reference scatter is .set():
    // LAST duplicate wins -> zero values whose index reappears later.
    int bid = blockIdx.y * gridDim.x + blockIdx.x;
    if (bid < N_ / 4) {
        __shared__ int sidx[4][K_];
        int t   = threadIdx.x;
        int lr  = t >> 6;
        int k   = t & 63;
        int row = bid * 4 + lr;
        int sv  = idx[row * K_ + k];
        sidx[lr][k] = sv;
        __syncthreads();
        bool keep = true;
        #pragma unroll 1
        for (int k2 = k + 1; k2 < K_; ++k2)
            if (sidx[lr][k2] == sv) keep = false;
        g_vals[row * K_ + k] = keep ? vals[row * K_ + k] : 0.0f;
    }
}

// ---------------------------------------------------------------------------
// Kernel 2: gather-FMA. fp16 W, fp32 v, fp32 FFMA accumulate (R3 dataflow),
// but 4 dims/thread (LDG.64) so register state halves NATURALLY ->
// more resident warps without clamping (R4 lesson), while unroll-8 keeps
// 8 independent loads in flight per thread (latency-exposure lesson).
//   grid = (N/RN row-tiles, D_IN/CD chunks), chunk = SLOW axis (L2 residency).
//   Block 256 = 64 dim-threads (4 dims) x 4 row-groups (4 rows each).
// ---------------------------------------------------------------------------
__global__ __launch_bounds__(256)
void gather_kernel(const int* __restrict__ idx,
                   const float* __restrict__ b_dec,
                   float* __restrict__ out) {
    __shared__ unsigned long long spack[RN][K_];  // lo32: W offset, hi32: f32 v bits

    int r0  = blockIdx.x * RN;
    int d0  = blockIdx.y * CD;
    int tid = threadIdx.x;

    #pragma unroll
    for (int i = tid; i < RN * K_; i += 256) {
        int   off = idx[r0 * K_ + i] * D_IN_;     // max 67.1M, fits 32-bit
        float v   = g_vals[r0 * K_ + i];
        spack[0][i] = (unsigned long long)(unsigned int)off
                    | ((unsigned long long)*reinterpret_cast<unsigned int*>(&v) << 32);
    }
    __syncthreads();

    int td = tid & 63;            // dim-thread
    int tr = tid >> 6;            // row group 0..3
    int d  = d0 + td * 4;         // 4 contiguous dims (8B fp16) per thread

    float4 bb = *reinterpret_cast<const float4*>(b_dec + d);

    const __half* Wt = g_Wth;

    #pragma unroll 1
    for (int i = 0; i < 4; ++i) {
        int r = tr * 4 + i;
        const unsigned long long* sp = spack[r];

        float4 acc = bb;

        #pragma unroll 8
        for (int k = 0; k < K_; ++k) {
            unsigned long long p = sp[k];         // LDS.64 broadcast
            int          off = (int)(unsigned int)p;
            unsigned int vb  = (unsigned int)(p >> 32);
            float v = *reinterpret_cast<float*>(&vb);
            uint2 w = *reinterpret_cast<const uint2*>(Wt + off + d);  // LDG.64
            float2 f0 = __half22float2(*reinterpret_cast<__half2*>(&w.x));
            float2 f1 = __half22float2(*reinterpret_cast<__half2*>(&w.y));
            acc.x = fmaf(v, f0.x, acc.x);
            acc.y = fmaf(v, f0.y, acc.y);
            acc.z = fmaf(v, f1.x, acc.z);
            acc.w = fmaf(v, f1.y, acc.w);
        }

        // Streaming store: don't let the 64MB output evict the W chunk in L2.
        __stcs(reinterpret_cast<float4*>(out + (size_t)(r0 + r) * D_IN_ + d),
               acc);
    }
}

// ---------------------------------------------------------------------------
// Launch. Inputs (metadata order): indices(int32 N*K), values(f32 N*K),
// W_dec(f32 D_IN*D_SAE), b_dec(f32 D_IN). Output: f32 N*D_IN.
// Graph-capturable: 2 plain kernel launches, zero allocation, zero sync.
// ---------------------------------------------------------------------------
extern "C" void kernel_launch(void* const* d_in, const int* in_sizes, int n_in,
                              void* d_out, int out_size) {
    const int*   indices = (const int*)  d_in[0];
    const float* values  = (const float*)d_in[1];
    const float* W       = (const float*)d_in[2];
    const float* b       = (const float*)d_in[3];
    float*       out     = (float*)d_out;

    dim3 tg(D_SAE_ / 32, D_IN_ / 64);
    transpose_dedupe_kernel<<<tg, 256>>>(W, indices, values);

    dim3 gg(N_ / RN, D_IN_ / CD);   // x = row tiles (fast), y = d-chunks (slow)
    gather_kernel<<<gg, 256>>>(indices, b, out);
}